// round 7
// baseline (speedup 1.0000x reference)
#include <cuda_runtime.h>
#include <cuda_bf16.h>
#include <math.h>
#include <stdint.h>

// Problem constants
#define B_  8
#define T_  1024
#define D_  512
#define H_  8
#define DK_ 64
#define P_  2047          // 2*T-1
#define NROW_ (B_*T_)     // 8192
#define ND_  (NROW_*D_)   // 4194304

// -------------------- device scratch (no allocs allowed) --------------------
__device__ float g_qn [ND_];
__device__ float g_kn [ND_];
__device__ float g_vn [ND_];
__device__ float g_qu [ND_];   // qh + pos_bias_u   layout [b, t, h, dk]
__device__ float g_qv [ND_];   // qh + pos_bias_v
__device__ float g_kh [ND_];   // layout [b, t, h, dk]
__device__ float g_vh [ND_];
__device__ float g_p  [(P_+1)*D_]; // layout [p, h, dk] (row 2047 = pad)
__device__ float g_ctx[ND_];   // attn @ V, layout [b, t, h, dk]

// ------------------------------ LayerNorm -----------------------------------
__global__ __launch_bounds__(256)
void ln_kernel(const float* __restrict__ x, const float* __restrict__ g,
               const float* __restrict__ bb, float* __restrict__ y)
{
    long row = blockIdx.x;
    const float2* xr = (const float2*)(x + row * D_);
    float2*       yr = (float2*)(y + row * D_);
    int tid = threadIdx.x;
    float2 v = xr[tid];
    float s  = v.x + v.y;
    float sq = v.x * v.x + v.y * v.y;

    __shared__ float rs[8], rq[8];
    #pragma unroll
    for (int o = 16; o > 0; o >>= 1) {
        s  += __shfl_xor_sync(0xffffffffu, s,  o);
        sq += __shfl_xor_sync(0xffffffffu, sq, o);
    }
    int wid = tid >> 5;
    if ((tid & 31) == 0) { rs[wid] = s; rq[wid] = sq; }
    __syncthreads();
    if (tid == 0) {
        float a = 0.f, b2 = 0.f;
        #pragma unroll
        for (int w = 0; w < 8; w++) { a += rs[w]; b2 += rq[w]; }
        rs[0] = a; rq[0] = b2;
    }
    __syncthreads();
    float mean = rs[0] * (1.0f / D_);
    float var  = rq[0] * (1.0f / D_) - mean * mean;
    float rstd = rsqrtf(var + 1e-5f);
    const float2* gv2 = (const float2*)g;
    const float2* bv2 = (const float2*)bb;
    float2 gv = gv2[tid], bv = bv2[tid];
    float2 o;
    o.x = (v.x - mean) * rstd * gv.x + bv.x;
    o.y = (v.y - mean) * rstd * gv.y + bv.y;
    yr[tid] = o;
}

// ------------------------- TF32 helpers --------------------------------------
__device__ __forceinline__ uint32_t f2tf(float f) {
    uint32_t u;
    asm("cvt.rna.tf32.f32 %0, %1;" : "=r"(u) : "f"(f));
    return u;
}

__device__ __forceinline__ void mma_tf32(float c[4], const uint32_t a[4],
                                         const uint32_t b[2]) {
    asm volatile(
        "mma.sync.aligned.m16n8k8.row.col.f32.tf32.tf32.f32 "
        "{%0,%1,%2,%3},{%4,%5,%6,%7},{%8,%9},{%0,%1,%2,%3};\n"
        : "+f"(c[0]), "+f"(c[1]), "+f"(c[2]), "+f"(c[3])
        : "r"(a[0]), "r"(a[1]), "r"(a[2]), "r"(a[3]), "r"(b[0]), "r"(b[1]));
}

__device__ __forceinline__ void cp16(float* dst_smem, const float* src, bool valid) {
    uint32_t d = (uint32_t)__cvta_generic_to_shared(dst_smem);
    int sz = valid ? 16 : 0;
    asm volatile("cp.async.cg.shared.global [%0], [%1], 16, %2;\n"
                 :: "r"(d), "l"(src), "r"(sz));
}
#define CP_COMMIT() asm volatile("cp.async.commit_group;\n" ::: "memory")
#define CP_WAIT0()  asm volatile("cp.async.wait_group 0;\n" ::: "memory")
#define CP_WAIT1()  asm volatile("cp.async.wait_group 1;\n" ::: "memory")

// ------------------------------ TF32 MMA GEMM --------------------------------
// (projections + FC) 3-stage cp.async pipeline.
template<int BM, int BN, int WM, int WN, bool TRANS_B>
__global__ __launch_bounds__(256)
void mma_gemm(const float* __restrict__ A, const float* __restrict__ Bm,
              float* __restrict__ C, float* __restrict__ C2,
              const float* __restrict__ bias1, const float* __restrict__ bias2,
              const float* __restrict__ Res,
              int M, int N, int K, int lda, int ldb, int ldc,
              float alpha)
{
    constexpr int BK = 16;
    constexpr int MT = WM / 16;
    constexpr int NT = WN / 8;
    constexpr int WCOLS = BN / WN;
    static_assert((BM / WM) * (BN / WN) == 8, "8 warps required");

    __shared__ float As[3][BM][BK + 4];
    __shared__ float Bs[3][TRANS_B ? BN : BK][TRANS_B ? (BK + 4) : (BN + 8)];

    int m0 = blockIdx.y * BM, n0 = blockIdx.x * BN;

    int tid  = threadIdx.x;
    int warp = tid >> 5, lane = tid & 31;
    int wm0 = (warp / WCOLS) * WM;
    int wn0 = (warp % WCOLS) * WN;

    auto ldg_async = [&](int k0, int buf) {
        #pragma unroll
        for (int it = 0; it < (BM * BK) / (4 * 256); it++) {
            int s = tid + it * 256;
            int row = s >> 2, kq = s & 3;
            int gm = m0 + row;
            cp16(&As[buf][row][kq * 4], A + (long)gm * lda + k0 + kq * 4, gm < M);
        }
        if (TRANS_B) {
            #pragma unroll
            for (int it = 0; it < (BN * BK) / (4 * 256); it++) {
                int s = tid + it * 256;
                int n = s >> 2, kq = s & 3;
                int gn = n0 + n;
                cp16(&Bs[buf][n][kq * 4], Bm + (long)gn * ldb + k0 + kq * 4, gn < N);
            }
        } else {
            #pragma unroll
            for (int it = 0; it < (BK * BN) / (4 * 256); it++) {
                int s = tid + it * 256;
                int kk = s / (BN / 4), nq = s % (BN / 4);
                cp16(&Bs[buf][kk][nq * 4],
                     Bm + (long)(k0 + kk) * ldb + n0 + nq * 4, true);
            }
        }
        CP_COMMIT();
    };

    float acc[MT][NT][4];
    #pragma unroll
    for (int i = 0; i < MT; i++)
        #pragma unroll
        for (int j = 0; j < NT; j++)
            #pragma unroll
            for (int e = 0; e < 4; e++) acc[i][j][e] = 0.f;

    const int nIter = K / BK;
    ldg_async(0, 0);
    if (nIter > 1) ldg_async(BK, 1);
    if (nIter > 1) { CP_WAIT1(); } else { CP_WAIT0(); }
    __syncthreads();

    for (int itk = 0; itk < nIter; itk++) {
        int buf = itk % 3;
        if (itk + 2 < nIter) ldg_async((itk + 2) * BK, (itk + 2) % 3);

        #pragma unroll
        for (int ks = 0; ks < 2; ks++) {
            const int kb = ks * 8;
            const int kc = kb + (lane & 3);
            uint32_t af[MT][4];
            uint32_t bf[NT][2];
            #pragma unroll
            for (int mt = 0; mt < MT; mt++) {
                int mrow = wm0 + mt * 16 + (lane >> 2);
                af[mt][0] = f2tf(As[buf][mrow    ][kc    ]);
                af[mt][1] = f2tf(As[buf][mrow + 8][kc    ]);
                af[mt][2] = f2tf(As[buf][mrow    ][kc + 4]);
                af[mt][3] = f2tf(As[buf][mrow + 8][kc + 4]);
            }
            #pragma unroll
            for (int nt = 0; nt < NT; nt++) {
                int ncol = wn0 + nt * 8 + (lane >> 2);
                if (TRANS_B) {
                    bf[nt][0] = f2tf(Bs[buf][ncol][kc    ]);
                    bf[nt][1] = f2tf(Bs[buf][ncol][kc + 4]);
                } else {
                    bf[nt][0] = f2tf(Bs[buf][kc    ][ncol]);
                    bf[nt][1] = f2tf(Bs[buf][kc + 4][ncol]);
                }
            }
            #pragma unroll
            for (int mt = 0; mt < MT; mt++)
                #pragma unroll
                for (int nt = 0; nt < NT; nt++)
                    mma_tf32(acc[mt][nt], af[mt], bf[nt]);
        }

        if (itk + 1 < nIter) {
            if (itk + 2 < nIter) { CP_WAIT1(); } else { CP_WAIT0(); }
        }
        __syncthreads();
    }

    auto emit = [&](int gm, int gn, float v) {
        if (gm < M && gn < N) {
            float val = v * alpha;
            if (Res) val += Res[(long)gm * ldc + gn];
            if (C2) {
                C [(long)gm * ldc + gn] = val + bias1[gn];
                C2[(long)gm * ldc + gn] = val + bias2[gn];
            } else {
                C[(long)gm * ldc + gn] = val + (bias1 ? bias1[gn] : 0.f);
            }
        }
    };
    #pragma unroll
    for (int mt = 0; mt < MT; mt++) {
        #pragma unroll
        for (int nt = 0; nt < NT; nt++) {
            int gm = m0 + wm0 + mt * 16 + (lane >> 2);
            int gn = n0 + wn0 + nt * 8 + 2 * (lane & 3);
            emit(gm,     gn,     acc[mt][nt][0]);
            emit(gm,     gn + 1, acc[mt][nt][1]);
            emit(gm + 8, gn,     acc[mt][nt][2]);
            emit(gm + 8, gn + 1, acc[mt][nt][3]);
        }
    }
}

// ===================== FUSED ATTENTION (2 CTAs/SM) ==========================
// One CTA: (b,h), 16 query rows, 256 threads (8 warps). S strip [16 x 1024]
// in smem; 64-row K/V/P tiles double-buffered. Q fragments hoisted.
#define S_STRIDE 1028
#define K_STRIDE 68
#define V_STRIDE 72
#define SMEM_FLOATS (16*S_STRIDE + 2*64*V_STRIDE + 2*16*K_STRIDE)

__global__ __launch_bounds__(256, 2)
void fused_attn(const float* __restrict__ qu, const float* __restrict__ qv,
                const float* __restrict__ kh, const float* __restrict__ vh,
                const float* __restrict__ pbuf, const int* __restrict__ mask,
                float* __restrict__ attn, float* __restrict__ ctx)
{
    extern __shared__ float sm[];
    float* S   = sm;                          // [16][1028]
    float* KV0 = sm + 16 * S_STRIDE;          // [64][72] (K/P use stride 68)
    float* KV1 = KV0 + 64 * V_STRIDE;
    float* Qu  = KV1 + 64 * V_STRIDE;         // [16][68]
    float* Qv  = Qu + 16 * K_STRIDE;

    const int i0 = blockIdx.x * 16;
    const int z  = blockIdx.y;                // b*H + h
    const int b  = z >> 3, h = z & 7;
    const int tid = threadIdx.x;
    const int w = tid >> 5, lane = tid & 31;
    const float scale = 0.125f;
    const float NEG = __int_as_float(0xff7fffff);   // -FLT_MAX sentinel

    // ---- load Qu, Qv tiles (16 x 64): 256 slots each ----
    {
        int r = tid >> 4, kq = tid & 15;
        long base = ((long)(b * T_ + i0 + r) * D_ + h * DK_ + kq * 4);
        cp16(&Qu[r * K_STRIDE + kq * 4], qu + base, true);
        cp16(&Qv[r * K_STRIDE + kq * 4], qv + base, true);
    }
    CP_COMMIT();

    auto load_k = [&](int jt, float* buf) {          // 64 rows x 64 cols
        #pragma unroll
        for (int it = 0; it < 4; it++) {
            int s = tid + it * 256;
            int n = s >> 4, kq = s & 15;
            cp16(&buf[n * K_STRIDE + kq * 4],
                 kh + ((long)(b * T_ + jt * 64 + n) * D_ + h * DK_ + kq * 4), true);
        }
        CP_COMMIT();
    };
    auto load_v = [&](int jt, float* buf) {
        #pragma unroll
        for (int it = 0; it < 4; it++) {
            int s = tid + it * 256;
            int n = s >> 4, kq = s & 15;
            cp16(&buf[n * V_STRIDE + kq * 4],
                 vh + ((long)(b * T_ + jt * 64 + n) * D_ + h * DK_ + kq * 4), true);
        }
        CP_COMMIT();
    };
    auto load_p = [&](int pt0, float* buf) {
        #pragma unroll
        for (int it = 0; it < 4; it++) {
            int s = tid + it * 256;
            int n = s >> 4, kq = s & 15;
            int p = pt0 + n;
            cp16(&buf[n * K_STRIDE + kq * 4],
                 pbuf + ((long)p * D_ + h * DK_ + kq * 4), p <= P_ - 1);
        }
        CP_COMMIT();
    };

    const int r0 = lane >> 2;                 // A-fragment base row (m16)

    // ---------------- Phase 1: ac = scale * Qu @ K^T ----------------
    load_k(0, KV0);
    CP_WAIT0();
    __syncthreads();

    {
        uint32_t au[8][4];                    // hoisted Qu fragments
        #pragma unroll
        for (int kk = 0; kk < 8; kk++) {
            int kc = kk * 8 + (lane & 3);
            au[kk][0] = f2tf(Qu[r0 * K_STRIDE + kc]);
            au[kk][1] = f2tf(Qu[(r0 + 8) * K_STRIDE + kc]);
            au[kk][2] = f2tf(Qu[r0 * K_STRIDE + kc + 4]);
            au[kk][3] = f2tf(Qu[(r0 + 8) * K_STRIDE + kc + 4]);
        }

        for (int jt = 0; jt < 16; jt++) {
            float* cur = (jt & 1) ? KV1 : KV0;
            float* nxt = (jt & 1) ? KV0 : KV1;
            if (jt + 1 < 16) load_k(jt + 1, nxt);

            float acc[4] = {0.f, 0.f, 0.f, 0.f};
            const int ncol = w * 8 + (lane >> 2);
            #pragma unroll
            for (int kk = 0; kk < 8; kk++) {
                int kc = kk * 8 + (lane & 3);
                uint32_t bf[2] = { f2tf(cur[ncol * K_STRIDE + kc]),
                                   f2tf(cur[ncol * K_STRIDE + kc + 4]) };
                mma_tf32(acc, au[kk], bf);
            }
            int c0 = jt * 64 + w * 8 + 2 * (lane & 3);
            *(float2*)&S[r0 * S_STRIDE + c0] =
                make_float2(acc[0] * scale, acc[1] * scale);
            *(float2*)&S[(r0 + 8) * S_STRIDE + c0] =
                make_float2(acc[2] * scale, acc[3] * scale);
            if (jt + 1 < 16) CP_WAIT0();
            __syncthreads();
        }
    }

    // ------------- Phase 2: bd scatter-add over p-window -------------
    // p in [pbase, pbase + 17*64); j = p - (T-1) + i
    const int pbase = (T_ - 1) - (i0 + 15);
    load_p(pbase, KV0);
    {
        uint32_t av[8][4];                    // hoisted Qv fragments
        #pragma unroll
        for (int kk = 0; kk < 8; kk++) {
            int kc = kk * 8 + (lane & 3);
            av[kk][0] = f2tf(Qv[r0 * K_STRIDE + kc]);
            av[kk][1] = f2tf(Qv[(r0 + 8) * K_STRIDE + kc]);
            av[kk][2] = f2tf(Qv[r0 * K_STRIDE + kc + 4]);
            av[kk][3] = f2tf(Qv[(r0 + 8) * K_STRIDE + kc + 4]);
        }
        CP_WAIT0();
        __syncthreads();

        for (int pt = 0; pt < 17; pt++) {
            float* cur = (pt & 1) ? KV1 : KV0;
            float* nxt = (pt & 1) ? KV0 : KV1;
            if (pt + 1 < 17) load_p(pbase + (pt + 1) * 64, nxt);

            float acc[4] = {0.f, 0.f, 0.f, 0.f};
            const int ncol = w * 8 + (lane >> 2);
            #pragma unroll
            for (int kk = 0; kk < 8; kk++) {
                int kc = kk * 8 + (lane & 3);
                uint32_t bf[2] = { f2tf(cur[ncol * K_STRIDE + kc]),
                                   f2tf(cur[ncol * K_STRIDE + kc + 4]) };
                mma_tf32(acc, av[kk], bf);
            }
            const int pt0 = pbase + pt * 64;
            const int c0 = w * 8 + 2 * (lane & 3);
            #pragma unroll
            for (int e = 0; e < 4; e++) {
                int r = r0 + (e >> 1) * 8;
                int p = pt0 + c0 + (e & 1);
                int j = p - (T_ - 1) + i0 + r;
                if ((unsigned)j < (unsigned)T_)
                    S[r * S_STRIDE + j] += acc[e] * scale;
            }
            if (pt + 1 < 17) CP_WAIT0();
            __syncthreads();
        }
    }

    // -------- prefetch V tile 0 (overlaps softmax) --------
    load_v(0, KV0);

    // ---------------- Phase 3: softmax (reg-resident rows) ----------------
    #pragma unroll
    for (int t = 0; t < 2; t++) {
        int r = w + 8 * t;
        int i = i0 + r;
        const int4*   mrow = (const int4*)(mask + ((long)b * T_ + i) * T_);
        float4*       srow = (float4*)(S + r * S_STRIDE);
        float4*       arow = (float4*)(attn + ((long)z * T_ + i) * T_);

        float4 vals[8];
        float lmax = NEG;
        #pragma unroll
        for (int e = 0; e < 8; e++) {
            int idx = e * 32 + lane;
            float4 v = srow[idx];
            int4   m = mrow[idx];
            v.x = (m.x == 0) ? NEG : v.x;
            v.y = (m.y == 0) ? NEG : v.y;
            v.z = (m.z == 0) ? NEG : v.z;
            v.w = (m.w == 0) ? NEG : v.w;
            vals[e] = v;
            lmax = fmaxf(lmax, fmaxf(fmaxf(v.x, v.y), fmaxf(v.z, v.w)));
        }
        #pragma unroll
        for (int o = 16; o > 0; o >>= 1)
            lmax = fmaxf(lmax, __shfl_xor_sync(0xffffffffu, lmax, o));

        if (lmax == NEG) {                     // fully masked row
            float4 zero = make_float4(0.f, 0.f, 0.f, 0.f);
            #pragma unroll
            for (int e = 0; e < 8; e++) {
                int idx = e * 32 + lane;
                srow[idx] = zero;
                arow[idx] = zero;
            }
            continue;
        }
        float sum = 0.f;
        #pragma unroll
        for (int e = 0; e < 8; e++) {
            float4 v = vals[e];
            v.x = __expf(v.x - lmax); v.y = __expf(v.y - lmax);
            v.z = __expf(v.z - lmax); v.w = __expf(v.w - lmax);
            vals[e] = v;
            sum += (v.x + v.y) + (v.z + v.w);
        }
        #pragma unroll
        for (int o = 16; o > 0; o >>= 1)
            sum += __shfl_xor_sync(0xffffffffu, sum, o);
        float inv = 1.0f / sum;
        #pragma unroll
        for (int e = 0; e < 8; e++) {
            int idx = e * 32 + lane;
            float4 v = vals[e];
            v.x *= inv; v.y *= inv; v.z *= inv; v.w *= inv;
            srow[idx] = v;
            arow[idx] = v;
        }
    }
    CP_WAIT0();
    __syncthreads();

    // ---------------- Phase 4: O = S @ V -> ctx ----------------
    float oacc[4] = {0.f, 0.f, 0.f, 0.f};
    const int vn = w * 8 + (lane >> 2);

    for (int jt = 0; jt < 16; jt++) {
        float* cur = (jt & 1) ? KV1 : KV0;
        float* nxt = (jt & 1) ? KV0 : KV1;
        if (jt + 1 < 16) load_v(jt + 1, nxt);

        #pragma unroll
        for (int kk = 0; kk < 8; kk++) {
            int kc = kk * 8 + (lane & 3);
            uint32_t af[4] = { f2tf(S[r0 * S_STRIDE + jt * 64 + kc]),
                               f2tf(S[(r0 + 8) * S_STRIDE + jt * 64 + kc]),
                               f2tf(S[r0 * S_STRIDE + jt * 64 + kc + 4]),
                               f2tf(S[(r0 + 8) * S_STRIDE + jt * 64 + kc + 4]) };
            uint32_t bf[2] = { f2tf(cur[kc * V_STRIDE + vn]),
                               f2tf(cur[(kc + 4) * V_STRIDE + vn]) };
            mma_tf32(oacc, af, bf);
        }
        if (jt + 1 < 16) CP_WAIT0();
        __syncthreads();
    }

    const int n0 = w * 8 + 2 * (lane & 3);
    long o0 = (long)(b * T_ + i0 + r0) * D_ + h * DK_ + n0;
    long o1 = (long)(b * T_ + i0 + r0 + 8) * D_ + h * DK_ + n0;
    *(float2*)&ctx[o0] = make_float2(oacc[0], oacc[1]);
    *(float2*)&ctx[o1] = make_float2(oacc[2], oacc[3]);
}

// ------------------------------ launch ---------------------------------------
extern "C" void kernel_launch(void* const* d_in, const int* in_sizes, int n_in,
                              void* d_out, int out_size)
{
    const float* q    = (const float*)d_in[0];
    const float* k    = (const float*)d_in[1];
    const float* v    = (const float*)d_in[2];
    const float* pos  = (const float*)d_in[3];
    const int*   mask = (const int*)  d_in[4];
    const float* lnqg = (const float*)d_in[5],  *lnqb = (const float*)d_in[6];
    const float* lnkg = (const float*)d_in[7],  *lnkb = (const float*)d_in[8];
    const float* lnvg = (const float*)d_in[9],  *lnvb = (const float*)d_in[10];
    const float* wq   = (const float*)d_in[11], *wk   = (const float*)d_in[12];
    const float* wv   = (const float*)d_in[13], *wpos = (const float*)d_in[14];
    const float* wfc  = (const float*)d_in[15];
    const float* pbu  = (const float*)d_in[16], *pbv  = (const float*)d_in[17];

    float* out  = (float*)d_out;                 // [B,T,D]
    float* attn = out + (size_t)ND_;             // [B,H,T,T]

    float *qn,*kn,*vn,*qu,*qvb,*kh,*vh,*pb,*ctx;
    cudaGetSymbolAddress((void**)&qn,  g_qn);
    cudaGetSymbolAddress((void**)&kn,  g_kn);
    cudaGetSymbolAddress((void**)&vn,  g_vn);
    cudaGetSymbolAddress((void**)&qu,  g_qu);
    cudaGetSymbolAddress((void**)&qvb, g_qv);
    cudaGetSymbolAddress((void**)&kh,  g_kh);
    cudaGetSymbolAddress((void**)&vh,  g_vh);
    cudaGetSymbolAddress((void**)&pb,  g_p);
    cudaGetSymbolAddress((void**)&ctx, g_ctx);

    static const size_t fused_smem = SMEM_FLOATS * sizeof(float);
    cudaFuncSetAttribute(fused_attn,
                         cudaFuncAttributeMaxDynamicSharedMemorySize,
                         (int)fused_smem);

    // LayerNorms
    ln_kernel<<<NROW_, 256>>>(q, lnqg, lnqb, qn);
    ln_kernel<<<NROW_, 256>>>(k, lnkg, lnkb, kn);
    ln_kernel<<<NROW_, 256>>>(v, lnvg, lnvb, vn);

    // Q projection with dual bias epilogue -> qu = qh+u, qv = qh+v
    mma_gemm<128,128,64,32,true><<<dim3(4,64,1),256>>>(
        qn, wq, qu, qvb, pbu, pbv, nullptr,
        NROW_, D_, D_, D_, D_, D_, 1.f);
    // K, V projections
    mma_gemm<128,128,64,32,true><<<dim3(4,64,1),256>>>(
        kn, wk, kh, nullptr, nullptr, nullptr, nullptr,
        NROW_, D_, D_, D_, D_, D_, 1.f);
    mma_gemm<128,128,64,32,true><<<dim3(4,64,1),256>>>(
        vn, wv, vh, nullptr, nullptr, nullptr, nullptr,
        NROW_, D_, D_, D_, D_, D_, 1.f);
    // pos projection  (M = 2047)
    mma_gemm<128,128,64,32,true><<<dim3(4,16,1),256>>>(
        pos, wpos, pb, nullptr, nullptr, nullptr, nullptr,
        P_, D_, D_, D_, D_, D_, 1.f);

    // fused attention: ac + bd(rel-shift) + softmax + attn-write + PV
    fused_attn<<<dim3(64, 64), 256, fused_smem>>>(
        qu, qvb, kh, vh, pb, mask, attn, ctx);

    // out = ctx @ Wfc^T + residual(q)
    mma_gemm<128,128,64,32,true><<<dim3(4,64,1),256>>>(
        ctx, wfc, out, nullptr, nullptr, nullptr, q,
        NROW_, D_, D_, D_, D_, D_, 1.f);
}

// round 8
// speedup vs baseline: 1.1028x; 1.1028x over previous
#include <cuda_runtime.h>
#include <cuda_bf16.h>
#include <math.h>
#include <stdint.h>

// Problem constants
#define B_  8
#define T_  1024
#define D_  512
#define H_  8
#define DK_ 64
#define P_  2047          // 2*T-1
#define NROW_ (B_*T_)     // 8192
#define ND_  (NROW_*D_)   // 4194304

// -------------------- device scratch (no allocs allowed) --------------------
__device__ float g_qn [ND_];
__device__ float g_kn [ND_];
__device__ float g_vn [ND_];
__device__ float g_qu [ND_];   // qh + pos_bias_u (tf32-rounded) [b,t,h,dk]
__device__ float g_qv [ND_];   // qh + pos_bias_v (tf32-rounded)
__device__ float g_kh [ND_];   // tf32-rounded
__device__ float g_vh [ND_];   // tf32-rounded
__device__ float g_p  [(P_+1)*D_]; // tf32-rounded [p, h, dk] (row 2047 = pad)
__device__ float g_ctx[ND_];   // attn @ V (fp32)

// ------------------------------ LayerNorm -----------------------------------
__global__ __launch_bounds__(256)
void ln_kernel(const float* __restrict__ x, const float* __restrict__ g,
               const float* __restrict__ bb, float* __restrict__ y)
{
    long row = blockIdx.x;
    const float2* xr = (const float2*)(x + row * D_);
    float2*       yr = (float2*)(y + row * D_);
    int tid = threadIdx.x;
    float2 v = xr[tid];
    float s  = v.x + v.y;
    float sq = v.x * v.x + v.y * v.y;

    __shared__ float rs[8], rq[8];
    #pragma unroll
    for (int o = 16; o > 0; o >>= 1) {
        s  += __shfl_xor_sync(0xffffffffu, s,  o);
        sq += __shfl_xor_sync(0xffffffffu, sq, o);
    }
    int wid = tid >> 5;
    if ((tid & 31) == 0) { rs[wid] = s; rq[wid] = sq; }
    __syncthreads();
    if (tid == 0) {
        float a = 0.f, b2 = 0.f;
        #pragma unroll
        for (int w = 0; w < 8; w++) { a += rs[w]; b2 += rq[w]; }
        rs[0] = a; rq[0] = b2;
    }
    __syncthreads();
    float mean = rs[0] * (1.0f / D_);
    float var  = rq[0] * (1.0f / D_) - mean * mean;
    float rstd = rsqrtf(var + 1e-5f);
    const float2* gv2 = (const float2*)g;
    const float2* bv2 = (const float2*)bb;
    float2 gv = gv2[tid], bv = bv2[tid];
    float2 o;
    o.x = (v.x - mean) * rstd * gv.x + bv.x;
    o.y = (v.y - mean) * rstd * gv.y + bv.y;
    yr[tid] = o;
}

// ------------------------- TF32 helpers --------------------------------------
__device__ __forceinline__ uint32_t f2tf(float f) {
    uint32_t u;
    asm("cvt.rna.tf32.f32 %0, %1;" : "=r"(u) : "f"(f));
    return u;
}

__device__ __forceinline__ void mma_tf32(float c[4], const uint32_t a[4],
                                         const uint32_t b[2]) {
    asm volatile(
        "mma.sync.aligned.m16n8k8.row.col.f32.tf32.tf32.f32 "
        "{%0,%1,%2,%3},{%4,%5,%6,%7},{%8,%9},{%0,%1,%2,%3};\n"
        : "+f"(c[0]), "+f"(c[1]), "+f"(c[2]), "+f"(c[3])
        : "r"(a[0]), "r"(a[1]), "r"(a[2]), "r"(a[3]), "r"(b[0]), "r"(b[1]));
}

__device__ __forceinline__ void cp16(float* dst_smem, const float* src, bool valid) {
    uint32_t d = (uint32_t)__cvta_generic_to_shared(dst_smem);
    int sz = valid ? 16 : 0;
    asm volatile("cp.async.cg.shared.global [%0], [%1], 16, %2;\n"
                 :: "r"(d), "l"(src), "r"(sz));
}
#define CP_COMMIT() asm volatile("cp.async.commit_group;\n" ::: "memory")
#define CP_WAIT0()  asm volatile("cp.async.wait_group 0;\n" ::: "memory")
#define CP_WAIT1()  asm volatile("cp.async.wait_group 1;\n" ::: "memory")

// bit-copy load (no conversion) of a tf32-prerounded float from smem
__device__ __forceinline__ uint32_t ldu(const float* p) {
    return __float_as_uint(*p);
}

// ------------------------------ TF32 MMA GEMM --------------------------------
// (projections + FC) 3-stage cp.async pipeline. CVT_OUT: store tf32-rounded.
template<int BM, int BN, int WM, int WN, bool TRANS_B, bool CVT_OUT>
__global__ __launch_bounds__(256)
void mma_gemm(const float* __restrict__ A, const float* __restrict__ Bm,
              float* __restrict__ C, float* __restrict__ C2,
              const float* __restrict__ bias1, const float* __restrict__ bias2,
              const float* __restrict__ Res,
              int M, int N, int K, int lda, int ldb, int ldc,
              float alpha)
{
    constexpr int BK = 16;
    constexpr int MT = WM / 16;
    constexpr int NT = WN / 8;
    constexpr int WCOLS = BN / WN;
    static_assert((BM / WM) * (BN / WN) == 8, "8 warps required");

    __shared__ float As[3][BM][BK + 4];
    __shared__ float Bs[3][TRANS_B ? BN : BK][TRANS_B ? (BK + 4) : (BN + 8)];

    int m0 = blockIdx.y * BM, n0 = blockIdx.x * BN;

    int tid  = threadIdx.x;
    int warp = tid >> 5, lane = tid & 31;
    int wm0 = (warp / WCOLS) * WM;
    int wn0 = (warp % WCOLS) * WN;

    auto ldg_async = [&](int k0, int buf) {
        #pragma unroll
        for (int it = 0; it < (BM * BK) / (4 * 256); it++) {
            int s = tid + it * 256;
            int row = s >> 2, kq = s & 3;
            int gm = m0 + row;
            cp16(&As[buf][row][kq * 4], A + (long)gm * lda + k0 + kq * 4, gm < M);
        }
        if (TRANS_B) {
            #pragma unroll
            for (int it = 0; it < (BN * BK) / (4 * 256); it++) {
                int s = tid + it * 256;
                int n = s >> 2, kq = s & 3;
                int gn = n0 + n;
                cp16(&Bs[buf][n][kq * 4], Bm + (long)gn * ldb + k0 + kq * 4, gn < N);
            }
        } else {
            #pragma unroll
            for (int it = 0; it < (BK * BN) / (4 * 256); it++) {
                int s = tid + it * 256;
                int kk = s / (BN / 4), nq = s % (BN / 4);
                cp16(&Bs[buf][kk][nq * 4],
                     Bm + (long)(k0 + kk) * ldb + n0 + nq * 4, true);
            }
        }
        CP_COMMIT();
    };

    float acc[MT][NT][4];
    #pragma unroll
    for (int i = 0; i < MT; i++)
        #pragma unroll
        for (int j = 0; j < NT; j++)
            #pragma unroll
            for (int e = 0; e < 4; e++) acc[i][j][e] = 0.f;

    const int nIter = K / BK;
    ldg_async(0, 0);
    if (nIter > 1) ldg_async(BK, 1);
    if (nIter > 1) { CP_WAIT1(); } else { CP_WAIT0(); }
    __syncthreads();

    for (int itk = 0; itk < nIter; itk++) {
        int buf = itk % 3;
        if (itk + 2 < nIter) ldg_async((itk + 2) * BK, (itk + 2) % 3);

        #pragma unroll
        for (int ks = 0; ks < 2; ks++) {
            const int kb = ks * 8;
            const int kc = kb + (lane & 3);
            uint32_t af[MT][4];
            uint32_t bf[NT][2];
            #pragma unroll
            for (int mt = 0; mt < MT; mt++) {
                int mrow = wm0 + mt * 16 + (lane >> 2);
                af[mt][0] = f2tf(As[buf][mrow    ][kc    ]);
                af[mt][1] = f2tf(As[buf][mrow + 8][kc    ]);
                af[mt][2] = f2tf(As[buf][mrow    ][kc + 4]);
                af[mt][3] = f2tf(As[buf][mrow + 8][kc + 4]);
            }
            #pragma unroll
            for (int nt = 0; nt < NT; nt++) {
                int ncol = wn0 + nt * 8 + (lane >> 2);
                if (TRANS_B) {
                    bf[nt][0] = f2tf(Bs[buf][ncol][kc    ]);
                    bf[nt][1] = f2tf(Bs[buf][ncol][kc + 4]);
                } else {
                    bf[nt][0] = f2tf(Bs[buf][kc    ][ncol]);
                    bf[nt][1] = f2tf(Bs[buf][kc + 4][ncol]);
                }
            }
            #pragma unroll
            for (int mt = 0; mt < MT; mt++)
                #pragma unroll
                for (int nt = 0; nt < NT; nt++)
                    mma_tf32(acc[mt][nt], af[mt], bf[nt]);
        }

        if (itk + 1 < nIter) {
            if (itk + 2 < nIter) { CP_WAIT1(); } else { CP_WAIT0(); }
        }
        __syncthreads();
    }

    auto emit = [&](int gm, int gn, float v) {
        if (gm < M && gn < N) {
            float val = v * alpha;
            if (Res) val += Res[(long)gm * ldc + gn];
            if (C2) {
                float v1 = val + bias1[gn];
                float v2 = val + bias2[gn];
                if (CVT_OUT) { v1 = __uint_as_float(f2tf(v1)); v2 = __uint_as_float(f2tf(v2)); }
                C [(long)gm * ldc + gn] = v1;
                C2[(long)gm * ldc + gn] = v2;
            } else {
                float v1 = val + (bias1 ? bias1[gn] : 0.f);
                if (CVT_OUT) v1 = __uint_as_float(f2tf(v1));
                C[(long)gm * ldc + gn] = v1;
            }
        }
    };
    #pragma unroll
    for (int mt = 0; mt < MT; mt++) {
        #pragma unroll
        for (int nt = 0; nt < NT; nt++) {
            int gm = m0 + wm0 + mt * 16 + (lane >> 2);
            int gn = n0 + wn0 + nt * 8 + 2 * (lane & 3);
            emit(gm,     gn,     acc[mt][nt][0]);
            emit(gm,     gn + 1, acc[mt][nt][1]);
            emit(gm + 8, gn,     acc[mt][nt][2]);
            emit(gm + 8, gn + 1, acc[mt][nt][3]);
        }
    }
}

// ===================== FUSED ATTENTION ======================================
// One CTA: (b,h), 32 query rows, 512 threads. S strip [32 x 1024] in smem.
// All MMA operands (qu/qv/kh/vh/p and post-softmax S) pre-rounded to tf32,
// so mainloops are pure LDS + MMA (no cvt).
#define S_STRIDE 1028
#define K_STRIDE 68
#define V_STRIDE 72
#define SMEM_FLOATS (32*S_STRIDE + 2*128*V_STRIDE + 2*32*K_STRIDE)

__global__ __launch_bounds__(512)
void fused_attn(const float* __restrict__ qu, const float* __restrict__ qv,
                const float* __restrict__ kh, const float* __restrict__ vh,
                const float* __restrict__ pbuf, const int* __restrict__ mask,
                float* __restrict__ attn, float* __restrict__ ctx)
{
    extern __shared__ float sm[];
    float* S   = sm;                          // [32][1028]
    float* KV0 = sm + 32 * S_STRIDE;          // [128][72] (K/P use stride 68)
    float* KV1 = KV0 + 128 * V_STRIDE;
    float* Qu  = KV1 + 128 * V_STRIDE;        // [32][68]
    float* Qv  = Qu + 32 * K_STRIDE;

    const int i0 = blockIdx.x * 32;
    const int z  = blockIdx.y;                // b*H + h
    const int b  = z >> 3, h = z & 7;
    const int tid = threadIdx.x;
    const int w = tid >> 5, lane = tid & 31;
    const float scale = 0.125f;
    const float NEG = __int_as_float(0xff7fffff);   // -FLT_MAX sentinel

    // ---- load Qu, Qv tiles (32 x 64) ----
    {
        int r = tid >> 4, kq = tid & 15;
        long base = ((long)(b * T_ + i0 + r) * D_ + h * DK_ + kq * 4);
        cp16(&Qu[r * K_STRIDE + kq * 4], qu + base, true);
        cp16(&Qv[r * K_STRIDE + kq * 4], qv + base, true);
    }
    CP_COMMIT();

    auto load_k = [&](int jt, float* buf) {
        #pragma unroll
        for (int it = 0; it < 4; it++) {
            int s = tid + it * 512;
            int n = s >> 4, kq = s & 15;
            cp16(&buf[n * K_STRIDE + kq * 4],
                 kh + ((long)(b * T_ + jt * 128 + n) * D_ + h * DK_ + kq * 4), true);
        }
        CP_COMMIT();
    };
    auto load_v = [&](int jt, float* buf) {
        #pragma unroll
        for (int it = 0; it < 4; it++) {
            int s = tid + it * 512;
            int n = s >> 4, kq = s & 15;
            cp16(&buf[n * V_STRIDE + kq * 4],
                 vh + ((long)(b * T_ + jt * 128 + n) * D_ + h * DK_ + kq * 4), true);
        }
        CP_COMMIT();
    };
    auto load_p = [&](int pt0, float* buf) {
        #pragma unroll
        for (int it = 0; it < 4; it++) {
            int s = tid + it * 512;
            int n = s >> 4, kq = s & 15;
            int p = pt0 + n;
            cp16(&buf[n * K_STRIDE + kq * 4],
                 pbuf + ((long)p * D_ + h * DK_ + kq * 4), p <= P_ - 1);
        }
        CP_COMMIT();
    };

    // warp mapping for score phases: mh = row-half(16), ne = col-strip of 16
    const int mh = w & 1, ne = w >> 1;
    const int r0 = mh * 16 + (lane >> 2);

    // ---------------- Phase 1: ac = scale * Qu @ K^T ----------------
    load_k(0, KV0);
    CP_WAIT0();
    __syncthreads();

    {
        uint32_t au[8][4];                   // hoisted Qu fragments (bit loads)
        #pragma unroll
        for (int kk = 0; kk < 8; kk++) {
            int kc = kk * 8 + (lane & 3);
            au[kk][0] = ldu(&Qu[r0 * K_STRIDE + kc]);
            au[kk][1] = ldu(&Qu[(r0 + 8) * K_STRIDE + kc]);
            au[kk][2] = ldu(&Qu[r0 * K_STRIDE + kc + 4]);
            au[kk][3] = ldu(&Qu[(r0 + 8) * K_STRIDE + kc + 4]);
        }

        for (int jt = 0; jt < 8; jt++) {
            float* cur = (jt & 1) ? KV1 : KV0;
            float* nxt = (jt & 1) ? KV0 : KV1;
            if (jt + 1 < 8) load_k(jt + 1, nxt);

            float acc[2][4] = {{0.f,0.f,0.f,0.f},{0.f,0.f,0.f,0.f}};
            #pragma unroll
            for (int kk = 0; kk < 8; kk++) {
                int kc = kk * 8 + (lane & 3);
                #pragma unroll
                for (int nt = 0; nt < 2; nt++) {
                    int ncol = ne * 16 + nt * 8 + (lane >> 2);
                    uint32_t bf[2] = { ldu(&cur[ncol * K_STRIDE + kc]),
                                       ldu(&cur[ncol * K_STRIDE + kc + 4]) };
                    mma_tf32(acc[nt], au[kk], bf);
                }
            }
            #pragma unroll
            for (int nt = 0; nt < 2; nt++) {
                int c0 = jt * 128 + ne * 16 + nt * 8 + 2 * (lane & 3);
                *(float2*)&S[r0 * S_STRIDE + c0] =
                    make_float2(acc[nt][0] * scale, acc[nt][1] * scale);
                *(float2*)&S[(r0 + 8) * S_STRIDE + c0] =
                    make_float2(acc[nt][2] * scale, acc[nt][3] * scale);
            }
            if (jt + 1 < 8) CP_WAIT0();
            __syncthreads();
        }
    }

    // ------------- Phase 2: bd scatter-add over p-window -------------
    const int pbase = (T_ - 1) - (i0 + 31);
    load_p(pbase, KV0);
    {
        uint32_t av[8][4];
        #pragma unroll
        for (int kk = 0; kk < 8; kk++) {
            int kc = kk * 8 + (lane & 3);
            av[kk][0] = ldu(&Qv[r0 * K_STRIDE + kc]);
            av[kk][1] = ldu(&Qv[(r0 + 8) * K_STRIDE + kc]);
            av[kk][2] = ldu(&Qv[r0 * K_STRIDE + kc + 4]);
            av[kk][3] = ldu(&Qv[(r0 + 8) * K_STRIDE + kc + 4]);
        }
        CP_WAIT0();
        __syncthreads();

        for (int pt = 0; pt < 9; pt++) {
            float* cur = (pt & 1) ? KV1 : KV0;
            float* nxt = (pt & 1) ? KV0 : KV1;
            if (pt + 1 < 9) load_p(pbase + (pt + 1) * 128, nxt);

            float acc[2][4] = {{0.f,0.f,0.f,0.f},{0.f,0.f,0.f,0.f}};
            #pragma unroll
            for (int kk = 0; kk < 8; kk++) {
                int kc = kk * 8 + (lane & 3);
                #pragma unroll
                for (int nt = 0; nt < 2; nt++) {
                    int ncol = ne * 16 + nt * 8 + (lane >> 2);
                    uint32_t bf[2] = { ldu(&cur[ncol * K_STRIDE + kc]),
                                       ldu(&cur[ncol * K_STRIDE + kc + 4]) };
                    mma_tf32(acc[nt], av[kk], bf);
                }
            }
            const int pt0 = pbase + pt * 128;
            #pragma unroll
            for (int nt = 0; nt < 2; nt++) {
                int c0 = ne * 16 + nt * 8 + 2 * (lane & 3);
                #pragma unroll
                for (int e = 0; e < 4; e++) {
                    int r = r0 + (e >> 1) * 8;
                    int p = pt0 + c0 + (e & 1);
                    int j = p - (T_ - 1) + i0 + r;
                    if ((unsigned)j < (unsigned)T_)
                        S[r * S_STRIDE + j] += acc[nt][e] * scale;
                }
            }
            if (pt + 1 < 9) CP_WAIT0();
            __syncthreads();
        }
    }

    // -------- prefetch V tile 0 (overlaps softmax) --------
    load_v(0, KV0);

    // ------ Phase 3: softmax; attn gets fp32, S gets tf32-rounded ------
    #pragma unroll
    for (int t = 0; t < 2; t++) {
        int r = w + 16 * t;
        int i = i0 + r;
        const int4*   mrow = (const int4*)(mask + ((long)b * T_ + i) * T_);
        float4*       srow = (float4*)(S + r * S_STRIDE);
        float4*       arow = (float4*)(attn + ((long)z * T_ + i) * T_);

        float4 vals[8];
        float lmax = NEG;
        #pragma unroll
        for (int e = 0; e < 8; e++) {
            int idx = e * 32 + lane;
            float4 v = srow[idx];
            int4   m = mrow[idx];
            v.x = (m.x == 0) ? NEG : v.x;
            v.y = (m.y == 0) ? NEG : v.y;
            v.z = (m.z == 0) ? NEG : v.z;
            v.w = (m.w == 0) ? NEG : v.w;
            vals[e] = v;
            lmax = fmaxf(lmax, fmaxf(fmaxf(v.x, v.y), fmaxf(v.z, v.w)));
        }
        #pragma unroll
        for (int o = 16; o > 0; o >>= 1)
            lmax = fmaxf(lmax, __shfl_xor_sync(0xffffffffu, lmax, o));

        if (lmax == NEG) {
            float4 zero = make_float4(0.f, 0.f, 0.f, 0.f);
            #pragma unroll
            for (int e = 0; e < 8; e++) {
                int idx = e * 32 + lane;
                srow[idx] = zero;
                arow[idx] = zero;
            }
            continue;
        }
        float sum = 0.f;
        #pragma unroll
        for (int e = 0; e < 8; e++) {
            float4 v = vals[e];
            v.x = __expf(v.x - lmax); v.y = __expf(v.y - lmax);
            v.z = __expf(v.z - lmax); v.w = __expf(v.w - lmax);
            vals[e] = v;
            sum += (v.x + v.y) + (v.z + v.w);
        }
        #pragma unroll
        for (int o = 16; o > 0; o >>= 1)
            sum += __shfl_xor_sync(0xffffffffu, sum, o);
        float inv = 1.0f / sum;
        #pragma unroll
        for (int e = 0; e < 8; e++) {
            int idx = e * 32 + lane;
            float4 v = vals[e];
            v.x *= inv; v.y *= inv; v.z *= inv; v.w *= inv;
            arow[idx] = v;                       // exact fp32 out
            float4 vt;                           // tf32-rounded smem copy
            vt.x = __uint_as_float(f2tf(v.x));
            vt.y = __uint_as_float(f2tf(v.y));
            vt.z = __uint_as_float(f2tf(v.z));
            vt.w = __uint_as_float(f2tf(v.w));
            srow[idx] = vt;
        }
    }
    CP_WAIT0();
    __syncthreads();

    // ---------------- Phase 4: O = S @ V -> ctx ----------------
    const int mt = w >> 3, nt = w & 7;     // 2 x 8 warp grid over [32 x 64]
    float oacc[4] = {0.f, 0.f, 0.f, 0.f};
    const int r4 = mt * 16 + (lane >> 2);
    const int vn = nt * 8 + (lane >> 2);

    for (int jt = 0; jt < 8; jt++) {
        float* cur = (jt & 1) ? KV1 : KV0;
        float* nxt = (jt & 1) ? KV0 : KV1;
        if (jt + 1 < 8) load_v(jt + 1, nxt);

        #pragma unroll
        for (int kk = 0; kk < 16; kk++) {
            int kc = kk * 8 + (lane & 3);
            uint32_t af[4] = { ldu(&S[r4 * S_STRIDE + jt * 128 + kc]),
                               ldu(&S[(r4 + 8) * S_STRIDE + jt * 128 + kc]),
                               ldu(&S[r4 * S_STRIDE + jt * 128 + kc + 4]),
                               ldu(&S[(r4 + 8) * S_STRIDE + jt * 128 + kc + 4]) };
            uint32_t bf[2] = { ldu(&cur[kc * V_STRIDE + vn]),
                               ldu(&cur[(kc + 4) * V_STRIDE + vn]) };
            mma_tf32(oacc, af, bf);
        }
        if (jt + 1 < 8) CP_WAIT0();
        __syncthreads();
    }

    const int n0 = nt * 8 + 2 * (lane & 3);
    long o0 = (long)(b * T_ + i0 + r4) * D_ + h * DK_ + n0;
    long o1 = (long)(b * T_ + i0 + r4 + 8) * D_ + h * DK_ + n0;
    *(float2*)&ctx[o0] = make_float2(oacc[0], oacc[1]);
    *(float2*)&ctx[o1] = make_float2(oacc[2], oacc[3]);
}

// ------------------------------ launch ---------------------------------------
extern "C" void kernel_launch(void* const* d_in, const int* in_sizes, int n_in,
                              void* d_out, int out_size)
{
    const float* q    = (const float*)d_in[0];
    const float* k    = (const float*)d_in[1];
    const float* v    = (const float*)d_in[2];
    const float* pos  = (const float*)d_in[3];
    const int*   mask = (const int*)  d_in[4];
    const float* lnqg = (const float*)d_in[5],  *lnqb = (const float*)d_in[6];
    const float* lnkg = (const float*)d_in[7],  *lnkb = (const float*)d_in[8];
    const float* lnvg = (const float*)d_in[9],  *lnvb = (const float*)d_in[10];
    const float* wq   = (const float*)d_in[11], *wk   = (const float*)d_in[12];
    const float* wv   = (const float*)d_in[13], *wpos = (const float*)d_in[14];
    const float* wfc  = (const float*)d_in[15];
    const float* pbu  = (const float*)d_in[16], *pbv  = (const float*)d_in[17];

    float* out  = (float*)d_out;                 // [B,T,D]
    float* attn = out + (size_t)ND_;             // [B,H,T,T]

    float *qn,*kn,*vn,*qu,*qvb,*kh,*vh,*pb,*ctx;
    cudaGetSymbolAddress((void**)&qn,  g_qn);
    cudaGetSymbolAddress((void**)&kn,  g_kn);
    cudaGetSymbolAddress((void**)&vn,  g_vn);
    cudaGetSymbolAddress((void**)&qu,  g_qu);
    cudaGetSymbolAddress((void**)&qvb, g_qv);
    cudaGetSymbolAddress((void**)&kh,  g_kh);
    cudaGetSymbolAddress((void**)&vh,  g_vh);
    cudaGetSymbolAddress((void**)&pb,  g_p);
    cudaGetSymbolAddress((void**)&ctx, g_ctx);

    static const size_t fused_smem = SMEM_FLOATS * sizeof(float);
    cudaFuncSetAttribute(fused_attn,
                         cudaFuncAttributeMaxDynamicSharedMemorySize,
                         (int)fused_smem);

    // LayerNorms
    ln_kernel<<<NROW_, 256>>>(q, lnqg, lnqb, qn);
    ln_kernel<<<NROW_, 256>>>(k, lnkg, lnkb, kn);
    ln_kernel<<<NROW_, 256>>>(v, lnvg, lnvb, vn);

    // Q projection with dual bias epilogue -> qu/qv (tf32-rounded)
    mma_gemm<128,128,64,32,true,true><<<dim3(4,64,1),256>>>(
        qn, wq, qu, qvb, pbu, pbv, nullptr,
        NROW_, D_, D_, D_, D_, D_, 1.f);
    // K, V projections (tf32-rounded outputs)
    mma_gemm<128,128,64,32,true,true><<<dim3(4,64,1),256>>>(
        kn, wk, kh, nullptr, nullptr, nullptr, nullptr,
        NROW_, D_, D_, D_, D_, D_, 1.f);
    mma_gemm<128,128,64,32,true,true><<<dim3(4,64,1),256>>>(
        vn, wv, vh, nullptr, nullptr, nullptr, nullptr,
        NROW_, D_, D_, D_, D_, D_, 1.f);
    // pos projection  (M = 2047, tf32-rounded)
    mma_gemm<128,128,64,32,true,true><<<dim3(4,16,1),256>>>(
        pos, wpos, pb, nullptr, nullptr, nullptr, nullptr,
        P_, D_, D_, D_, D_, D_, 1.f);

    // fused attention: ac + bd(rel-shift) + softmax + attn-write + PV
    fused_attn<<<dim3(32, 64), 512, fused_smem>>>(
        qu, qvb, kh, vh, pb, mask, attn, ctx);

    // out = ctx @ Wfc^T + residual(q)  (fp32 output)
    mma_gemm<128,128,64,32,true,false><<<dim3(4,64,1),256>>>(
        ctx, wfc, out, nullptr, nullptr, nullptr, q,
        NROW_, D_, D_, D_, D_, D_, 1.f);
}